// round 14
// baseline (speedup 1.0000x reference)
#include <cuda_runtime.h>
#include <cuda_bf16.h>
#include <cstdint>

#define BATCH 4
#define SEQ   1024
#define DIN   1024
#define HD    64
#define NE    8
#define NHEAD 4
#define COUT  (HD*NE*NHEAD)    // 2048
#define MROWS (BATCH*SEQ)      // 4096
#define NBEH  (BATCH*NE*NHEAD) // 128

#define QSCALE 0.18033688f     // 0.125 * log2(e), folded into q at projection

// ---------------------------------------------------------------------------
// Scratch (no allocations allowed)
// ---------------------------------------------------------------------------
__device__ float g_part[(size_t)4096 * SEQ];            // per-block partials, 16 MB

__device__ __nv_bfloat16 g_xh[(size_t)MROWS * DIN];     // x (bf16)
__device__ __nv_bfloat16 g_wth[2][(size_t)COUT * DIN];  // W^T (q,k) bf16

// q/k bf16, layout [beh][d][s]  (q pre-scaled by QSCALE)
__device__ __nv_bfloat16 g_qh[(size_t)NBEH * HD * SEQ];
__device__ __nv_bfloat16 g_kh[(size_t)NBEH * HD * SEQ];

// ---------------------------------------------------------------------------
// sm_80+ primitives
// ---------------------------------------------------------------------------
__device__ __forceinline__ uint32_t smem_u32(const void* p) {
    uint32_t a;
    asm("{ .reg .u64 t; cvta.to.shared.u64 t, %1; cvt.u32.u64 %0, t; }" : "=r"(a) : "l"(p));
    return a;
}
__device__ __forceinline__ void ldm_x4(uint32_t* r, uint32_t addr) {
    asm volatile("ldmatrix.sync.aligned.m8n8.x4.shared.b16 {%0,%1,%2,%3}, [%4];"
        : "=r"(r[0]), "=r"(r[1]), "=r"(r[2]), "=r"(r[3]) : "r"(addr));
}
__device__ __forceinline__ void ldm_x4t(uint32_t* r, uint32_t addr) {
    asm volatile("ldmatrix.sync.aligned.m8n8.x4.trans.shared.b16 {%0,%1,%2,%3}, [%4];"
        : "=r"(r[0]), "=r"(r[1]), "=r"(r[2]), "=r"(r[3]) : "r"(addr));
}
__device__ __forceinline__ void mma_bf16(float* d, const uint32_t* a, const uint32_t* b) {
    asm volatile("mma.sync.aligned.m16n8k16.row.col.f32.bf16.bf16.f32 "
        "{%0,%1,%2,%3}, {%4,%5,%6,%7}, {%8,%9}, {%0,%1,%2,%3};"
        : "+f"(d[0]), "+f"(d[1]), "+f"(d[2]), "+f"(d[3])
        : "r"(a[0]), "r"(a[1]), "r"(a[2]), "r"(a[3]), "r"(b[0]), "r"(b[1]));
}
__device__ __forceinline__ void cp16(uint32_t dst, const void* src) {
    asm volatile("cp.async.cg.shared.global [%0], [%1], 16;" :: "r"(dst), "l"(src));
}
__device__ __forceinline__ float ex2(float x) {
    float y; asm("ex2.approx.ftz.f32 %0, %1;" : "=f"(y) : "f"(x)); return y;
}
#define CP_COMMIT() asm volatile("cp.async.commit_group;" ::: "memory")
#define CP_WAIT1()  asm volatile("cp.async.wait_group 1;" ::: "memory")
#define CP_WAIT0()  asm volatile("cp.async.wait_group 0;" ::: "memory")

// ---------------------------------------------------------------------------
// Convert x -> bf16
// ---------------------------------------------------------------------------
__global__ __launch_bounds__(256)
void convert_x_kernel(const float* __restrict__ x)
{
    int i = blockIdx.x * 256 + threadIdx.x;
    float4 v = ((const float4*)x)[i];
    __nv_bfloat162* ph = (__nv_bfloat162*)g_xh;
    ph[i * 2 + 0] = __nv_bfloat162(__float2bfloat16(v.x), __float2bfloat16(v.y));
    ph[i * 2 + 1] = __nv_bfloat162(__float2bfloat16(v.z), __float2bfloat16(v.w));
}

// ---------------------------------------------------------------------------
// Convert + transpose W: Wt[n][k] = bf16(W[k][n])
// ---------------------------------------------------------------------------
__global__ __launch_bounds__(256)
void convert_wt_kernel(const float* __restrict__ Wq, const float* __restrict__ Wk)
{
    __shared__ float sm[32][33];
    const float* W = blockIdx.z ? Wk : Wq;
    __nv_bfloat16* oh = g_wth[blockIdx.z];
    int n0 = blockIdx.x * 32, k0 = blockIdx.y * 32;
    int tx = threadIdx.x & 31, ty = threadIdx.x >> 5;
#pragma unroll
    for (int j = 0; j < 4; j++)
        sm[ty + j * 8][tx] = W[(size_t)(k0 + ty + j * 8) * COUT + n0 + tx];
    __syncthreads();
#pragma unroll
    for (int j = 0; j < 4; j++) {
        int row = ty + j * 8;
        oh[(size_t)(n0 + row) * DIN + k0 + tx] = __float2bfloat16(sm[tx][row]);
    }
}

// ---------------------------------------------------------------------------
// mma.sync projection GEMM: C = xh@Wh + b, bf16 out. BK=64, 3-stage pipeline,
// ONE __syncthreads per chunk (prefetch distance 2, issued after the sync).
// z: 0 -> Q (g_qh, pre-scaled by QSCALE), 1 -> K (g_kh). Writes [beh][d][s].
// ---------------------------------------------------------------------------
#define SROWB   144                    // 64 bf16 = 128 B + 16 pad (conflict-free)
#define TILE_B  (128 * SROWB)          // 18432
#define NT      2                      // staged tiles: Ah, Bh
#define STAGE_B (NT * TILE_B)          // 36864
#define PROJ_SMEM (3 * STAGE_B)        // 110592 (3 stages)

__device__ __forceinline__ void proj_prefetch(
    uint32_t sb, int stage, int k0, int t,
    const __nv_bfloat16* a_h, const __nv_bfloat16* b_h)
{
    uint32_t st = sb + stage * STAGE_B;
    const __nv_bfloat16* srcs[NT] = { a_h, b_h };
#pragma unroll
    for (int tile = 0; tile < NT; tile++)
#pragma unroll
        for (int j = 0; j < 4; j++) {
            int idx = t + j * 256;
            int row = idx >> 3, cc = idx & 7;
            cp16(st + tile * TILE_B + row * SROWB + cc * 16,
                 srcs[tile] + (size_t)row * DIN + k0 + cc * 8);
        }
    CP_COMMIT();
}

__global__ void __launch_bounds__(256, 2)
proj_mma_kernel(const float* __restrict__ bq, const float* __restrict__ bk)
{
    extern __shared__ char smc[];
    const uint32_t sb = smem_u32(smc);
    const int t = threadIdx.x, wid = t >> 5, lane = t & 31;
    const int m0 = blockIdx.x * 128, n0 = blockIdx.y * 128, z = blockIdx.z;
    const int wm = (wid & 3) * 32, wn = (wid >> 2) * 64;

    const __nv_bfloat16* a_h = g_xh + (size_t)m0 * DIN;
    const __nv_bfloat16* b_h = g_wth[z] + (size_t)n0 * DIN;
    const float* bias = z ? bk : bq;
    __nv_bfloat16* outp = z ? g_kh : g_qh;
    const float oscale = z ? 1.0f : QSCALE;

    float acc[2][8][4];
#pragma unroll
    for (int mi = 0; mi < 2; mi++)
#pragma unroll
        for (int ni = 0; ni < 8; ni++)
#pragma unroll
            for (int r = 0; r < 4; r++) acc[mi][ni][r] = 0.f;

    proj_prefetch(sb, 0, 0, t, a_h, b_h);
    proj_prefetch(sb, 1, 64, t, a_h, b_h);

    const int NCHUNK = DIN / 64;       // 16
    for (int c = 0; c < NCHUNK; ++c) {
        if (c == NCHUNK - 1) CP_WAIT0(); else CP_WAIT1();
        __syncthreads();               // single barrier: chunk c visible, buf (c+2)%3 free
        if (c + 2 < NCHUNK)
            proj_prefetch(sb, (c + 2) % 3, (c + 2) * 64, t, a_h, b_h);

        const uint32_t st  = sb + (c % 3) * STAGE_B;
        const uint32_t sAh = st, sBh = st + TILE_B;

#pragma unroll
        for (int kk = 0; kk < 64; kk += 16) {
            uint32_t ah[2][4];
            const int arow = wm + (lane & 15);
            const int acol = kk + (lane >> 4) * 8;
#pragma unroll
            for (int mi = 0; mi < 2; mi++)
                ldm_x4(ah[mi], sAh + (arow + mi * 16) * SROWB + acol * 2);
            const int g = lane >> 3;
            const int brow_off = (g >> 1) * 8 + (lane & 7);
            const int bcol = kk + (g & 1) * 8;
#pragma unroll
            for (int np = 0; np < 4; np++) {
                uint32_t bh[4];
                int brow = wn + np * 16 + brow_off;
                ldm_x4(bh, sBh + brow * SROWB + bcol * 2);
#pragma unroll
                for (int mi = 0; mi < 2; mi++)
#pragma unroll
                    for (int nq = 0; nq < 2; nq++)
                        mma_bf16(acc[mi][np * 2 + nq], ah[mi], &bh[nq * 2]);
            }
        }
    }

    // Epilogue: (bias + acc) * oscale, bf16 store to [beh][d][s]
#pragma unroll
    for (int mi = 0; mi < 2; mi++) {
        int r = wm + mi * 16 + (lane >> 2);
        int m = m0 + r;
        int b = m >> 10, s = m & 1023;
#pragma unroll
        for (int ni = 0; ni < 8; ni++) {
            int col = n0 + wn + ni * 8 + (lane & 3) * 2;
            float bv0 = __ldg(&bias[col]);
            float bv1 = __ldg(&bias[col + 1]);
            int d = col >> 5, e0 = col & 31;
            size_t o0 = ((size_t)(b * 32 + e0) * HD + d) * SEQ + s;
            size_t o1 = ((size_t)(b * 32 + e0 + 1) * HD + d) * SEQ + s;
            outp[o0]     = __float2bfloat16((acc[mi][ni][0] + bv0) * oscale);
            outp[o1]     = __float2bfloat16((acc[mi][ni][1] + bv1) * oscale);
            outp[o0 + 8] = __float2bfloat16((acc[mi][ni][2] + bv0) * oscale);
            outp[o1 + 8] = __float2bfloat16((acc[mi][ni][3] + bv1) * oscale);
        }
    }
}

// ---------------------------------------------------------------------------
// MMA attention v10: 1q x 8k warp layout, Q pre-scaled, K chunks of 128,
// double-buffered; pass-2 uses LDS.64. 2 CTAs/SM.
// ---------------------------------------------------------------------------
#define AQ_STR 80                     // 32 q * 2B + 16 pad
#define AK_STR 272                    // 128 k * 2B + 16 pad
#define AP_STR 2064                   // 1024 k * 2B + 16 pad
#define KBUF_B (64 * AK_STR)          // 17408
#define SQH 0                         // 64 x 80 = 5120
#define SKB 5120                      // 2 buffers -> +34816 = 39936
#define SP  39936                     // 32 * 2064 = 66048 -> 105984
#define SRED 105984                   // 32 rows x 8 warps x 4B = 1024
#define SRZ  107008                   // 32 x 4B = 128
#define ATTN_SMEM 107136

__device__ __forceinline__ void attn_prefetch_k(
    uint32_t sb, int buf, int ck, int t, const __nv_bfloat16* kh)
{
    uint32_t base = sb + SKB + buf * KBUF_B;
#pragma unroll
    for (int j = 0; j < 4; j++) {
        int f = t + j * 256;          // 0..1023
        int d = f >> 4, cc = f & 15;
        cp16(base + d * AK_STR + cc * 16, kh + (size_t)d * SEQ + ck + cc * 8);
    }
    CP_COMMIT();
}

__global__ void __launch_bounds__(256, 2) attn_mma_kernel()
{
    extern __shared__ char smc[];
    const uint32_t sb = smem_u32(smc);
    const int t = threadIdx.x, wid = t >> 5, lane = t & 31;
    const int bid = blockIdx.x, beh = bid >> 5, qt = bid & 31, i0 = qt * 32;

    const __nv_bfloat16* qh = g_qh + (size_t)beh * HD * SEQ;
    const __nv_bfloat16* kh = g_kh + (size_t)beh * HD * SEQ;

    // Stage Q [64 d][32 q] (uncommitted; joins K0's group)
    {
        int d = t >> 2, cc = t & 3;
        cp16(sb + SQH + d * AQ_STR + cc * 16, qh + (size_t)d * SEQ + i0 + cc * 8);
    }
    attn_prefetch_k(sb, 0, 0, t, kh);

    const int mat = lane >> 3, l7 = lane & 7;
    float rs[2][2] = {{0.f, 0.f}, {0.f, 0.f}};

    const int adrow_off = (mat >> 1) * 8 + l7;       // A: d-row offset within 16
    const int bdrow_off = (mat & 1) * 8 + l7;        // B: d-row offset within 16
    const int bn = (wid * 16 + (mat >> 1) * 8) * 2;  // warp's distinct k strip

    uint32_t qf[4][2][4];             // resident Q fragments [ds][mi]

    for (int c = 0; c < 8; c++) {
        if (c < 7) { attn_prefetch_k(sb, (c + 1) & 1, (c + 1) * 128, t, kh); CP_WAIT1(); }
        else       { CP_WAIT0(); }
        __syncthreads();

        if (c == 0) {                 // hoist all Q fragments once
#pragma unroll
            for (int ds = 0; ds < 4; ds++)
#pragma unroll
                for (int mi = 0; mi < 2; mi++)
                    ldm_x4t(qf[ds][mi], sb + SQH + (ds * 16 + adrow_off) * AQ_STR
                                        + (mi * 16 + (mat & 1) * 8) * 2);
        }

        float acc[2][2][4];           // [mi][ni]
#pragma unroll
        for (int mi = 0; mi < 2; mi++)
#pragma unroll
            for (int ni = 0; ni < 2; ni++)
#pragma unroll
                for (int r = 0; r < 4; r++) acc[mi][ni][r] = 0.f;

        const uint32_t kb = sb + SKB + (c & 1) * KBUF_B;
#pragma unroll
        for (int ds = 0; ds < 4; ds++) {
            uint32_t bh[4];           // 16d x 16k fragment (warp-private strip)
            ldm_x4t(bh, kb + (ds * 16 + bdrow_off) * AK_STR + bn);
#pragma unroll
            for (int mi = 0; mi < 2; mi++) {
                mma_bf16(acc[mi][0], qf[ds][mi], &bh[0]);
                mma_bf16(acc[mi][1], qf[ds][mi], &bh[2]);
            }
        }
        __syncthreads();

        // exp (scores pre-scaled) -> P (bf16 smem) + row-sum accumulate
        const int r0 = lane >> 2;
#pragma unroll
        for (int mi = 0; mi < 2; mi++) {
            const int row = mi * 16 + r0;
#pragma unroll
            for (int ni = 0; ni < 2; ni++) {
                float p0 = ex2(acc[mi][ni][0]);
                float p1 = ex2(acc[mi][ni][1]);
                float p2 = ex2(acc[mi][ni][2]);
                float p3 = ex2(acc[mi][ni][3]);
                rs[mi][0] += p0 + p1;
                rs[mi][1] += p2 + p3;
                const int col = c * 128 + wid * 16 + ni * 8 + (lane & 3) * 2;
                *(__nv_bfloat162*)(smc + SP + row * AP_STR + col * 2) =
                    __floats2bfloat162_rn(p0, p1);
                *(__nv_bfloat162*)(smc + SP + (row + 8) * AP_STR + col * 2) =
                    __floats2bfloat162_rn(p2, p3);
            }
        }
    }

    // Z: quad-reduce, per-warp deposit (8 partials per row), combine
    float* red = (float*)(smc + SRED);
    float* rZ  = (float*)(smc + SRZ);
#pragma unroll
    for (int mi = 0; mi < 2; mi++)
#pragma unroll
        for (int hf = 0; hf < 2; hf++) {
            float v = rs[mi][hf];
            v += __shfl_xor_sync(0xFFFFFFFF, v, 1);
            v += __shfl_xor_sync(0xFFFFFFFF, v, 2);
            if ((lane & 3) == 0) {
                int row = mi * 16 + (lane >> 2) + hf * 8;
                red[row * 8 + wid] = v;
            }
        }
    __syncthreads();
    if (t < 32) {
        float4 a = *(float4*)&red[t * 8];
        float4 b = *(float4*)&red[t * 8 + 4];
        rZ[t] = 1.f / (a.x + a.y + a.z + a.w + b.x + b.y + b.z + b.w);
    }
    __syncthreads();

    // Pass 2: out[k] = sum_i P[i][k] * rZ[i]; thread owns 4 consecutive k (LDS.64)
    float s0 = 0.f, s1 = 0.f, s2 = 0.f, s3 = 0.f;
#pragma unroll 8
    for (int i = 0; i < 32; i++) {
        float r = rZ[i];
        uint2 w = *(const uint2*)(smc + SP + i * AP_STR + t * 8);
        float2 f0 = __bfloat1622float2(*(__nv_bfloat162*)&w.x);
        float2 f1 = __bfloat1622float2(*(__nv_bfloat162*)&w.y);
        s0 += f0.x * r;  s1 += f0.y * r;
        s2 += f1.x * r;  s3 += f1.y * r;
    }
    float* gp = g_part + (size_t)bid * 1024;
    *(float4*)&gp[t * 4] = make_float4(s0, s1, s2, s3);
}

// ---------------------------------------------------------------------------
// Final reduce (coalesced): block = (b,e); threads sweep k; sum h(4) x qt(32)
// ---------------------------------------------------------------------------
__global__ __launch_bounds__(256)
void reduce_kernel(float* __restrict__ out)
{
    const int be = blockIdx.x;        // 0..31
    const int b = be >> 3, e = be & 7;
    const int t = threadIdx.x;
#pragma unroll
    for (int j = 0; j < 4; j++) {
        int k = t + j * 256;
        float s = 0.f;
#pragma unroll
        for (int h = 0; h < NHEAD; h++) {
            int beh = b * 32 + e * 4 + h;
            const float* base = g_part + (size_t)(beh * 32) * 1024 + k;
#pragma unroll
            for (int qt = 0; qt < 32; qt++)
                s += base[qt * 1024];
        }
        out[((size_t)b * 1024 + k) * 8 + e] = s;
    }
}

// ---------------------------------------------------------------------------
extern "C" void kernel_launch(void* const* d_in, const int* in_sizes, int n_in,
                              void* d_out, int out_size)
{
    const float* x  = (const float*)d_in[0];
    const float* Wq = (const float*)d_in[1];
    const float* bq = (const float*)d_in[2];
    const float* Wk = (const float*)d_in[3];
    const float* bk = (const float*)d_in[4];
    float* out = (float*)d_out;

    convert_x_kernel<<<(MROWS * DIN / 4) / 256, 256>>>(x);
    convert_wt_kernel<<<dim3(COUT / 32, DIN / 32, 2), 256>>>(Wq, Wk);

    cudaFuncSetAttribute(proj_mma_kernel, cudaFuncAttributeMaxDynamicSharedMemorySize, PROJ_SMEM);
    proj_mma_kernel<<<dim3(MROWS / 128, COUT / 128, 2), 256, PROJ_SMEM>>>(bq, bk);

    cudaFuncSetAttribute(attn_mma_kernel, cudaFuncAttributeMaxDynamicSharedMemorySize, ATTN_SMEM);
    attn_mma_kernel<<<4096, 256, ATTN_SMEM>>>();

    reduce_kernel<<<32, 256>>>(out);
}